// round 5
// baseline (speedup 1.0000x reference)
#include <cuda_runtime.h>

typedef unsigned long long u64;

#define NT 512
#define GRID_BLKS 129

// ---- chain block smem layout (floats) ----
// 4 slots: rm (64x68) + MT (64x68) = 8704 each
#define SLOT_F   8704
#define SV_OFF   (4 * SLOT_F)          // 34816: 4 x 64 s-vectors
#define SCR_OFF  (SV_OFF + 256)        // 35072: 4096 k-split scratch
#define SMEM_FLOATS (SCR_OFF + 4096)   // 39168 floats = 156672 B

// ---- conv block smem layout (floats) ----
#define C_W1S 0                        // 64 x 168
#define C_XS  10752                    // 3 x 8 x 72 = 1728
#define C_H0  12480                    // 64 x 132 = 8448
#define H0_LD 132
#define C_ADS 20928                    // 64 x 128 = 8192
#define C_SAS 29120                    // 64
#define C_B1S 29184                    // 64

__device__ float g_AD[8192];   // [c][2*o] duplicated pairs of A = W2^200
__device__ float g_sA[64];
__device__ int   g_flag = 0;
__device__ int   g_done = 0;

__device__ __forceinline__ u64 pk2(float a, float b) {
    u64 r; asm("mov.b64 %0, {%1, %2};" : "=l"(r) : "f"(a), "f"(b)); return r;
}
__device__ __forceinline__ float2 up2(u64 v) {
    float2 r; asm("mov.b64 {%0, %1}, %2;" : "=f"(r.x), "=f"(r.y) : "l"(v)); return r;
}
__device__ __forceinline__ void fma2(u64& d, u64 a, u64 b) {
    asm("fma.rn.f32x2 %0, %1, %2, %0;" : "+l"(d) : "l"(a), "l"(b));
}
__device__ __forceinline__ void fadd2(u64& d, u64 a) {
    asm("add.rn.f32x2 %0, %0, %1;" : "+l"(d) : "l"(a));
}

// ---------------------------------------------------------------------------
// Affine compose C = A o B:  C.P = A.P * B.P ; C.s = A.P * B.s + A.s
// Slot layout: rm[k*68+c] = M[k][c] (row-major), MT[k*68+r] = M[r][k].
// 16 warps: tile = w&7 (16 rows x 32 cols), h = w>>3 (k-half). Merge via scratch.
// ---------------------------------------------------------------------------
__device__ __forceinline__ void compose(float* sm, int ai, int bi, int ci, int t)
{
    const float* AT  = sm + ai * SLOT_F + 4352;
    const float* Brm = sm + bi * SLOT_F;
    float* Crm = sm + ci * SLOT_F;
    float* CT  = sm + ci * SLOT_F + 4352;
    const float* svA = sm + SV_OFF + ai * 64;
    const float* svB = sm + SV_OFF + bi * 64;
    float* svC = sm + SV_OFF + ci * 64;
    float* scr = sm + SCR_OFF;

    const int w = t >> 5, lane = t & 31;
    const int h = w >> 3, tile = w & 7;
    const int rbase = (tile & 3) * 16, cbase = (tile >> 2) * 32;
    const int ro = lane >> 2, co = lane & 3;
    const int r0 = rbase + ro * 2, c0 = cbase + co * 8;

    u64 acc[2][4] = {};
    const float* aP = AT  + (h * 32) * 68 + r0;
    const float* bP = Brm + (h * 32) * 68 + c0;
#pragma unroll 4
    for (int kk = 0; kk < 32; ++kk) {
        float2 a = *(const float2*)aP;
        ulonglong2 b0 = *(const ulonglong2*)bP;
        ulonglong2 b1 = *(const ulonglong2*)(bP + 4);
        u64 d0 = pk2(a.x, a.x), d1 = pk2(a.y, a.y);
        fma2(acc[0][0], d0, b0.x); fma2(acc[0][1], d0, b0.y);
        fma2(acc[0][2], d0, b1.x); fma2(acc[0][3], d0, b1.y);
        fma2(acc[1][0], d1, b0.x); fma2(acc[1][1], d1, b0.y);
        fma2(acc[1][2], d1, b1.x); fma2(acc[1][3], d1, b1.y);
        aP += 68; bP += 68;
    }

    if (h == 1) {
        float* sp = scr + (tile * 32 + lane) * 4;   // interleaved: conflict-free
        ulonglong2 v;
        v.x = acc[0][0]; v.y = acc[0][1]; *(ulonglong2*)(sp)        = v;
        v.x = acc[0][2]; v.y = acc[0][3]; *(ulonglong2*)(sp + 1024) = v;
        v.x = acc[1][0]; v.y = acc[1][1]; *(ulonglong2*)(sp + 2048) = v;
        v.x = acc[1][2]; v.y = acc[1][3]; *(ulonglong2*)(sp + 3072) = v;
    }
    __syncthreads();
    if (h == 0) {
        const float* sp = scr + (tile * 32 + lane) * 4;
        ulonglong2 p0 = *(const ulonglong2*)(sp);
        ulonglong2 p1 = *(const ulonglong2*)(sp + 1024);
        ulonglong2 p2 = *(const ulonglong2*)(sp + 2048);
        ulonglong2 p3 = *(const ulonglong2*)(sp + 3072);
        fadd2(acc[0][0], p0.x); fadd2(acc[0][1], p0.y);
        fadd2(acc[0][2], p1.x); fadd2(acc[0][3], p1.y);
        fadd2(acc[1][0], p2.x); fadd2(acc[1][1], p2.y);
        fadd2(acc[1][2], p3.x); fadd2(acc[1][3], p3.y);
        ulonglong2 v;
        v.x = acc[0][0]; v.y = acc[0][1]; *(ulonglong2*)(Crm + r0 * 68 + c0)           = v;
        v.x = acc[0][2]; v.y = acc[0][3]; *(ulonglong2*)(Crm + r0 * 68 + c0 + 4)       = v;
        v.x = acc[1][0]; v.y = acc[1][1]; *(ulonglong2*)(Crm + (r0 + 1) * 68 + c0)     = v;
        v.x = acc[1][2]; v.y = acc[1][3]; *(ulonglong2*)(Crm + (r0 + 1) * 68 + c0 + 4) = v;
#pragma unroll
        for (int j = 0; j < 4; ++j) {
            float2 e0 = up2(acc[0][j]);
            float2 e1 = up2(acc[1][j]);
            float2 u;
            u.x = e0.x; u.y = e1.x; *(float2*)(CT + (c0 + 2 * j)     * 68 + r0) = u;
            u.x = e0.y; u.y = e1.y; *(float2*)(CT + (c0 + 2 * j + 1) * 68 + r0) = u;
        }
    } else if (t < 320) {
        const int r = t - 256;
        float s = svA[r];
#pragma unroll 8
        for (int k = 0; k < 64; ++k)
            s = fmaf(AT[k * 68 + r], svB[k], s);
        svC[r] = s;
    }
    __syncthreads();
}

__global__ void __launch_bounds__(NT, 1)
fused(const float* __restrict__ x, const float* __restrict__ W1,
      const float* __restrict__ b1, const float* __restrict__ W2,
      const float* __restrict__ b2, float* __restrict__ out)
{
    extern __shared__ float sm[];
    const int t   = threadIdx.x;
    const int bid = blockIdx.x;

    if (bid == 0) {
        // ================= chain block =================
        for (int i = t; i < 4096; i += NT) {
            int r = i >> 6, c = i & 63;
            float v = W2[i];
            sm[r * 68 + c]        = v;   // slot0 rm
            sm[4352 + c * 68 + r] = v;   // slot0 MT
        }
        if (t < 64) sm[SV_OFF + t] = b2[t];
        __syncthreads();

        // addition chain: 2,4,8,16,24(16+8),25(24+1),50,100,200
        const signed char A_[9] = {0, 1, 2, 3, 2, 1, 2, 1, 2};
        const signed char B_[9] = {0, 1, 2, 3, 3, 0, 2, 1, 2};
        const signed char C_[9] = {1, 2, 3, 2, 1, 2, 1, 2, 1};
#pragma unroll 1
        for (int s = 0; s < 9; ++s)
            compose(sm, A_[s], B_[s], C_[s], t);

        // publish T200 (slot 1): AD dup layout + s
        const float* AT200 = sm + SLOT_F + 4352;
        for (int i = t; i < 8192; i += NT) {
            int c = i >> 7, o = (i & 127) >> 1;
            g_AD[i] = AT200[c * 68 + o];
        }
        if (t < 64) g_sA[t] = sm[SV_OFF + 64 + t];
        __threadfence();
        __syncthreads();
        if (t == 0) atomicExch(&g_flag, 1);
    } else {
        // ================= conv + apply block =================
        float* W1s = sm + C_W1S;
        float* xs  = sm + C_XS;
        float* h0  = sm + C_H0;
        float* ADs = sm + C_ADS;
        float* sAs = sm + C_SAS;
        float* b1s = sm + C_B1S;

        const int r0 = (bid - 1) * 2;
        const int bb = r0 >> 6, y0 = r0 & 63;   // both rows in same image

        for (int i = t; i < 10752; i += NT) {
            int m = i / 168, jp = i % 168;
            int ii = jp / 56, r = jp % 56, ky = r / 8, kx = r % 8;
            W1s[i] = (kx < 7) ? W1[m * 147 + ii * 49 + ky * 7 + kx] : 0.0f;
        }
        if (t < 64) b1s[t] = b1[t];
        for (int i = t; i < 1728; i += NT) {
            int ii = i / 576, rem = i % 576;
            int yy = rem / 72, xx = rem % 72;
            xs[i] = (xx < 70) ? x[((bb * 3 + ii) * 70 + (y0 + yy)) * 70 + xx] : 0.0f;
        }
        __syncthreads();

        // ---- conv: h0 = conv7x7(x, W1) + b1, 2 rows paired in f32x2 ----
        const int xq = t & 7, oc = t >> 3;
        const int x0 = xq * 8;

        u64 acc[8];
        {
            u64 bv = pk2(b1s[oc], b1s[oc]);
#pragma unroll
            for (int xi = 0; xi < 8; ++xi) acc[xi] = bv;
        }

#pragma unroll 1
        for (int ii = 0; ii < 3; ++ii) {
#pragma unroll 1
            for (int ky = 0; ky < 7; ++ky) {
                const float* p0 = xs + (ii * 8 + ky) * 72 + x0;
                const float* p1 = p0 + 72;
                float a0[16], a1[16];
#pragma unroll
                for (int q = 0; q < 4; ++q) {
                    float4 u = *(const float4*)(p0 + q * 4);
                    a0[q*4+0] = u.x; a0[q*4+1] = u.y; a0[q*4+2] = u.z; a0[q*4+3] = u.w;
                    float4 v = *(const float4*)(p1 + q * 4);
                    a1[q*4+0] = v.x; a1[q*4+1] = v.y; a1[q*4+2] = v.z; a1[q*4+3] = v.w;
                }
                u64 xwp[14];
#pragma unroll
                for (int i = 0; i < 14; ++i) xwp[i] = pk2(a0[i], a1[i]);

                const float* wq = W1s + oc * 168 + ii * 56 + ky * 8;
                float4 w0 = *(const float4*)(wq);
                float4 w1 = *(const float4*)(wq + 4);
                u64 wp[7];
                wp[0] = pk2(w0.x, w0.x); wp[1] = pk2(w0.y, w0.y);
                wp[2] = pk2(w0.z, w0.z); wp[3] = pk2(w0.w, w0.w);
                wp[4] = pk2(w1.x, w1.x); wp[5] = pk2(w1.y, w1.y);
                wp[6] = pk2(w1.z, w1.z);
#pragma unroll
                for (int kx = 0; kx < 7; ++kx)
#pragma unroll
                    for (int xi = 0; xi < 8; ++xi)
                        fma2(acc[xi], wp[kx], xwp[kx + xi]);
            }
        }

        // ---- h0 -> smem [c][px], px = row*64 + x ----
        {
            float2 v[8];
#pragma unroll
            for (int xi = 0; xi < 8; ++xi) v[xi] = up2(acc[xi]);
            float* hb = h0 + oc * H0_LD;
            *(float4*)(hb + x0)          = make_float4(v[0].x, v[1].x, v[2].x, v[3].x);
            *(float4*)(hb + x0 + 4)      = make_float4(v[4].x, v[5].x, v[6].x, v[7].x);
            *(float4*)(hb + 64 + x0)     = make_float4(v[0].y, v[1].y, v[2].y, v[3].y);
            *(float4*)(hb + 64 + x0 + 4) = make_float4(v[4].y, v[5].y, v[6].y, v[7].y);
        }
        __syncthreads();

        // ---- wait for chain ----
        if (t == 0) {
            while (atomicAdd(&g_flag, 0) == 0) __nanosleep(64);
            __threadfence();
        }
        __syncthreads();
        for (int i = t; i < 8192; i += NT) ADs[i] = __ldcg(&g_AD[i]);
        if (t < 64) sAs[t] = __ldcg(&g_sA[t]);
        __syncthreads();

        // ---- apply: out = A*h0 + sA  (2 oc x 8 px per thread) ----
        const int po = t >> 4, pq = t & 15;
        const int o0 = po * 2, px0 = pq * 8;

        u64 ap[2][4] = {};
#pragma unroll 4
        for (int c = 0; c < 64; ++c) {
            ulonglong2 ad  = *(const ulonglong2*)(ADs + c * 128 + 4 * po);
            ulonglong2 hv0 = *(const ulonglong2*)(h0 + c * H0_LD + px0);
            ulonglong2 hv1 = *(const ulonglong2*)(h0 + c * H0_LD + px0 + 4);
            fma2(ap[0][0], ad.x, hv0.x); fma2(ap[0][1], ad.x, hv0.y);
            fma2(ap[0][2], ad.x, hv1.x); fma2(ap[0][3], ad.x, hv1.y);
            fma2(ap[1][0], ad.y, hv0.x); fma2(ap[1][1], ad.y, hv0.y);
            fma2(ap[1][2], ad.y, hv1.x); fma2(ap[1][3], ad.y, hv1.y);
        }

        const int rr = px0 >> 6, xx0 = px0 & 63, yy = y0 + rr;
#pragma unroll
        for (int j = 0; j < 2; ++j) {
            int o = o0 + j;
            float sa = sAs[o];
            float2 v0 = up2(ap[j][0]), v1 = up2(ap[j][1]);
            float2 v2 = up2(ap[j][2]), v3 = up2(ap[j][3]);
            float* pd = out + ((bb * 64 + o) * 64 + yy) * 64 + xx0;
            *(float4*)(pd)     = make_float4(v0.x + sa, v0.y + sa, v1.x + sa, v1.y + sa);
            *(float4*)(pd + 4) = make_float4(v2.x + sa, v2.y + sa, v3.x + sa, v3.y + sa);
        }
    }

    // ---- self-resetting flags so graph replays start clean ----
    __syncthreads();
    if (t == 0) {
        __threadfence();
        int d = atomicAdd(&g_done, 1);
        if (d == GRID_BLKS - 1) {
            atomicExch(&g_flag, 0);
            atomicExch(&g_done, 0);
        }
    }
}

extern "C" void kernel_launch(void* const* d_in, const int* in_sizes, int n_in,
                              void* d_out, int out_size)
{
    (void)in_sizes; (void)n_in; (void)out_size;
    const float* x  = (const float*)d_in[0];
    const float* W1 = (const float*)d_in[1];
    const float* b1 = (const float*)d_in[2];
    const float* W2 = (const float*)d_in[3];
    const float* b2 = (const float*)d_in[4];
    float* out = (float*)d_out;

    const size_t smem = (size_t)SMEM_FLOATS * sizeof(float);
    cudaFuncSetAttribute(fused, cudaFuncAttributeMaxDynamicSharedMemorySize, (int)smem);
    fused<<<GRID_BLKS, NT, smem>>>(x, W1, b1, W2, b2, out);
}

// round 7
// speedup vs baseline: 1.1014x; 1.1014x over previous
#include <cuda_runtime.h>

typedef unsigned long long u64;

#define NT 512
#define N_CHAIN 4
#define GRID_BLKS 132   // 4 chain + 128 conv

// ---- conv smem layout (floats) ----
#define C_W1S 0                        // 64 x 168
#define C_XS  10752                    // 3 x 8 x 72 = 1728
#define C_H0  12480                    // 64 x 132 = 8448
#define H0_LD 132
#define C_ADS 20928                    // 64 x 128 = 8192
#define C_SAS 29120                    // 64
#define C_B1S 29184                    // 64
#define SMEM_FLOATS 29248

// ---- chain smem layout (floats) ----
// Bs [0,4224) 64x66 | As [4224,5248) 16x64 | scr [5248,9344) | sAs 9344 | sBs 9408

// ---- device scratch ----
__device__ float g_M[4][4096];   // chain matrix slots, row-major [r*64+c]
__device__ float g_sv[4][64];    // matching s-vectors
__device__ float g_AD[8192];     // published A = W2^200, dup layout [c][2*o]
__device__ float g_sA[64];
__device__ int   g_bar  = 0;     // monotonic: +N_CHAIN per completed stage
__device__ int   g_done = 0;

__device__ __forceinline__ u64 pk2(float a, float b) {
    u64 r; asm("mov.b64 %0, {%1, %2};" : "=l"(r) : "f"(a), "f"(b)); return r;
}
__device__ __forceinline__ float2 up2(u64 v) {
    float2 r; asm("mov.b64 {%0, %1}, %2;" : "=f"(r.x), "=f"(r.y) : "l"(v)); return r;
}
__device__ __forceinline__ void fma2(u64& d, u64 a, u64 b) {
    asm("fma.rn.f32x2 %0, %1, %2, %0;" : "+l"(d) : "l"(a), "l"(b));
}
__device__ __forceinline__ void fadd2(u64& d, u64 a) {
    asm("add.rn.f32x2 %0, %0, %1;" : "+l"(d) : "l"(a));
}

__global__ void __launch_bounds__(NT, 1)
fused(const float* __restrict__ x, const float* __restrict__ W1,
      const float* __restrict__ b1, const float* __restrict__ W2,
      const float* __restrict__ b2, float* __restrict__ out)
{
    extern __shared__ float sm[];
    const int t   = threadIdx.x;
    const int bid = blockIdx.x;

    if (bid < N_CHAIN) {
        // ================= chain blocks: 4 blocks x 16 rows =================
        float* Bs  = sm;           // 64 x 66
        float* As  = sm + 4224;    // 16 x 64
        float* scr = sm + 5248;    // 256 x 16B merge scratch
        float* sAs = sm + 9344;    // 64
        float* sBs = sm + 9408;    // 64

        // addition chain: 2,4,8,16,24(16+8),25(24+1),50,100,200 ; slot -1 = (W2,b2)
        const signed char A_[9] = {-1, 0, 1, 2, 3, 1, 3, 1, 3};
        const signed char B_[9] = {-1, 0, 1, 2, 2,-1, 3, 1, 3};
        const signed char C_[9] = { 0, 1, 2, 3, 1, 3, 1, 3, 0};  // [8]: publish

        const int kh = t >> 8;          // k half: 0/1
        const int rp = (t >> 5) & 7;    // row pair 0..7
        const int cp = t & 31;          // col pair 0..31
        const int c0 = 2 * cp;
        const int mergeIdx = rp * 32 + cp;

#pragma unroll 1
        for (int s = 0; s < 9; ++s) {
            if (s > 0) {
                if (t == 0) {
                    while (atomicAdd(&g_bar, 0) < N_CHAIN * s) __nanosleep(32);
                }
                __syncthreads();
            }
            const int ai = A_[s], bi = B_[s];
            const float* Ap  = (ai < 0) ? W2 : g_M[ai];
            const float* Bp  = (bi < 0) ? W2 : g_M[bi];
            const float* sAp = (ai < 0) ? b2 : g_sv[ai];
            const float* sBp = (bi < 0) ? b2 : g_sv[bi];

            // stage loads: full B (stride 66), this block's 16 A rows, s-vectors
            for (int i = t; i < 4096; i += NT)
                Bs[(i >> 6) * 66 + (i & 63)] = __ldcg(Bp + i);
            for (int i = t; i < 1024; i += NT)
                As[i] = __ldcg(Ap + bid * 1024 + i);
            if (t < 64) {
                sAs[t] = __ldcg(sAp + t);
                sBs[t] = __ldcg(sBp + t);
            }
            __syncthreads();

            // C[r][c0..c0+1] = sum_k A[r][k] * B[k][c0..c0+1], k-split by kh
            const float* ar0 = As + (rp * 2) * 64 + kh * 32;
            const float* ar1 = ar0 + 64;
            const float* bp  = Bs + (kh * 32) * 66 + c0;
            u64 acc0 = 0, acc1 = 0;
#pragma unroll 8
            for (int k = 0; k < 32; ++k) {
                float a0 = ar0[k], a1 = ar1[k];
                u64 bv = *(const u64*)bp;
                fma2(acc0, pk2(a0, a0), bv);
                fma2(acc1, pk2(a1, a1), bv);
                bp += 66;
            }

            if (kh == 1) {
                ulonglong2 v; v.x = acc0; v.y = acc1;
                *(ulonglong2*)(scr + mergeIdx * 4) = v;
            }
            __syncthreads();
            if (kh == 0) {
                ulonglong2 p = *(const ulonglong2*)(scr + mergeIdx * 4);
                fadd2(acc0, p.x);
                fadd2(acc1, p.y);
                const int r0 = bid * 16 + rp * 2, r1 = r0 + 1;
                float2 v0 = up2(acc0), v1 = up2(acc1);
                if (s < 8) {
                    __stcg((float2*)(g_M[C_[s]] + r0 * 64 + c0), v0);
                    __stcg((float2*)(g_M[C_[s]] + r1 * 64 + c0), v1);
                } else {
                    // publish dup layout g_AD[c][2o], g_AD[c][2o+1] = A[o][c]
                    __stcg((float2*)(g_AD + (c0)     * 128 + 2 * r0), make_float2(v0.x, v0.x));
                    __stcg((float2*)(g_AD + (c0 + 1) * 128 + 2 * r0), make_float2(v0.y, v0.y));
                    __stcg((float2*)(g_AD + (c0)     * 128 + 2 * r1), make_float2(v1.x, v1.x));
                    __stcg((float2*)(g_AD + (c0 + 1) * 128 + 2 * r1), make_float2(v1.y, v1.y));
                }
            }
            // s' = P_B * s_A + s_B  (powers of one map commute)
            if (bid == 0 && t < 64) {
                float ss = sBs[t];
#pragma unroll 8
                for (int k = 0; k < 64; ++k)
                    ss = fmaf(Bs[t * 66 + k], sAs[k], ss);
                if (s < 8) __stcg(g_sv[C_[s]] + t, ss);
                else       __stcg(g_sA + t, ss);
            }
            __threadfence();
            __syncthreads();
            if (t == 0) atomicAdd(&g_bar, 1);
        }
    } else {
        // ================= conv + apply blocks =================
        float* W1s = sm + C_W1S;
        float* xs  = sm + C_XS;
        float* h0  = sm + C_H0;
        float* ADs = sm + C_ADS;
        float* sAs = sm + C_SAS;
        float* b1s = sm + C_B1S;

        const int r0 = (bid - N_CHAIN) * 2;
        const int bb = r0 >> 6, y0 = r0 & 63;   // both rows in same image

        for (int i = t; i < 10752; i += NT) {
            int m = i / 168, jp = i % 168;
            int ii = jp / 56, r = jp % 56, ky = r / 8, kx = r % 8;
            W1s[i] = (kx < 7) ? W1[m * 147 + ii * 49 + ky * 7 + kx] : 0.0f;
        }
        if (t < 64) b1s[t] = b1[t];
        for (int i = t; i < 1728; i += NT) {
            int ii = i / 576, rem = i % 576;
            int yy = rem / 72, xx = rem % 72;
            xs[i] = (xx < 70) ? x[((bb * 3 + ii) * 70 + (y0 + yy)) * 70 + xx] : 0.0f;
        }
        __syncthreads();

        // ---- conv: h0 = conv7x7(x, W1) + b1, 2 rows paired in f32x2 ----
        const int xq = t & 7, oc = t >> 3;
        const int x0 = xq * 8;

        u64 acc[8];
        {
            u64 bv = pk2(b1s[oc], b1s[oc]);
#pragma unroll
            for (int xi = 0; xi < 8; ++xi) acc[xi] = bv;
        }

#pragma unroll 1
        for (int ii = 0; ii < 3; ++ii) {
#pragma unroll 1
            for (int ky = 0; ky < 7; ++ky) {
                const float* p0 = xs + (ii * 8 + ky) * 72 + x0;
                const float* p1 = p0 + 72;
                float a0[16], a1[16];
#pragma unroll
                for (int q = 0; q < 4; ++q) {
                    float4 u = *(const float4*)(p0 + q * 4);
                    a0[q*4+0] = u.x; a0[q*4+1] = u.y; a0[q*4+2] = u.z; a0[q*4+3] = u.w;
                    float4 v = *(const float4*)(p1 + q * 4);
                    a1[q*4+0] = v.x; a1[q*4+1] = v.y; a1[q*4+2] = v.z; a1[q*4+3] = v.w;
                }
                u64 xwp[14];
#pragma unroll
                for (int i = 0; i < 14; ++i) xwp[i] = pk2(a0[i], a1[i]);

                const float* wq = W1s + oc * 168 + ii * 56 + ky * 8;
                float4 w0 = *(const float4*)(wq);
                float4 w1 = *(const float4*)(wq + 4);
                u64 wp[7];
                wp[0] = pk2(w0.x, w0.x); wp[1] = pk2(w0.y, w0.y);
                wp[2] = pk2(w0.z, w0.z); wp[3] = pk2(w0.w, w0.w);
                wp[4] = pk2(w1.x, w1.x); wp[5] = pk2(w1.y, w1.y);
                wp[6] = pk2(w1.z, w1.z);
#pragma unroll
                for (int kx = 0; kx < 7; ++kx)
#pragma unroll
                    for (int xi = 0; xi < 8; ++xi)
                        fma2(acc[xi], wp[kx], xwp[kx + xi]);
            }
        }

        // ---- h0 -> smem [c][px], px = row*64 + x ----
        {
            float2 v[8];
#pragma unroll
            for (int xi = 0; xi < 8; ++xi) v[xi] = up2(acc[xi]);
            float* hb = h0 + oc * H0_LD;
            *(float4*)(hb + x0)          = make_float4(v[0].x, v[1].x, v[2].x, v[3].x);
            *(float4*)(hb + x0 + 4)      = make_float4(v[4].x, v[5].x, v[6].x, v[7].x);
            *(float4*)(hb + 64 + x0)     = make_float4(v[0].y, v[1].y, v[2].y, v[3].y);
            *(float4*)(hb + 64 + x0 + 4) = make_float4(v[4].y, v[5].y, v[6].y, v[7].y);
        }
        __syncthreads();

        // ---- wait for chain completion (9 stages x N_CHAIN arrivals) ----
        if (t == 0) {
            while (atomicAdd(&g_bar, 0) < 9 * N_CHAIN) __nanosleep(64);
        }
        __syncthreads();
        for (int i = t; i < 8192; i += NT) ADs[i] = __ldcg(&g_AD[i]);
        if (t < 64) sAs[t] = __ldcg(&g_sA[t]);
        __syncthreads();

        // ---- apply: out = A*h0 + sA  (2 oc x 8 px per thread) ----
        const int po = t >> 4, pq = t & 15;
        const int o0 = po * 2, px0 = pq * 8;

        u64 ap[2][4] = {};
#pragma unroll 4
        for (int c = 0; c < 64; ++c) {
            ulonglong2 ad  = *(const ulonglong2*)(ADs + c * 128 + 4 * po);
            ulonglong2 hv0 = *(const ulonglong2*)(h0 + c * H0_LD + px0);
            ulonglong2 hv1 = *(const ulonglong2*)(h0 + c * H0_LD + px0 + 4);
            fma2(ap[0][0], ad.x, hv0.x); fma2(ap[0][1], ad.x, hv0.y);
            fma2(ap[0][2], ad.x, hv1.x); fma2(ap[0][3], ad.x, hv1.y);
            fma2(ap[1][0], ad.y, hv0.x); fma2(ap[1][1], ad.y, hv0.y);
            fma2(ap[1][2], ad.y, hv1.x); fma2(ap[1][3], ad.y, hv1.y);
        }

        const int rr = px0 >> 6, xx0 = px0 & 63, yy = y0 + rr;
#pragma unroll
        for (int j = 0; j < 2; ++j) {
            int o = o0 + j;
            float sa = sAs[o];
            float2 v0 = up2(ap[j][0]), v1 = up2(ap[j][1]);
            float2 v2 = up2(ap[j][2]), v3 = up2(ap[j][3]);
            float* pd = out + ((bb * 64 + o) * 64 + yy) * 64 + xx0;
            *(float4*)(pd)     = make_float4(v0.x + sa, v0.y + sa, v1.x + sa, v1.y + sa);
            *(float4*)(pd + 4) = make_float4(v2.x + sa, v2.y + sa, v3.x + sa, v3.y + sa);
        }
    }

    // ---- self-resetting counters so graph replays start clean ----
    __syncthreads();
    if (t == 0) {
        __threadfence();
        int d = atomicAdd(&g_done, 1);
        if (d == GRID_BLKS - 1) {
            atomicExch(&g_bar, 0);
            atomicExch(&g_done, 0);
        }
    }
}

extern "C" void kernel_launch(void* const* d_in, const int* in_sizes, int n_in,
                              void* d_out, int out_size)
{
    (void)in_sizes; (void)n_in; (void)out_size;
    const float* x  = (const float*)d_in[0];
    const float* W1 = (const float*)d_in[1];
    const float* b1 = (const float*)d_in[2];
    const float* W2 = (const float*)d_in[3];
    const float* b2 = (const float*)d_in[4];
    float* out = (float*)d_out;

    const size_t smem = (size_t)SMEM_FLOATS * sizeof(float);
    cudaFuncSetAttribute(fused, cudaFuncAttributeMaxDynamicSharedMemorySize, (int)smem);
    fused<<<GRID_BLKS, NT, smem>>>(x, W1, b1, W2, b2, out);
}